// round 2
// baseline (speedup 1.0000x reference)
#include <cuda_runtime.h>
#include <cuda_bf16.h>
#include <cstdint>

// Problem constants
#define NB 8
#define NC 128
#define NHEADS 8
#define NN 16384            // H*W
#define HK 16               // channels per head
#define NBH 64              // NB*NHEADS

// Kernel-1 tiling
#define TN 256              // n-tile held in smem
#define PAD 260             // padded row stride (floats), multiple of 4 for float4
#define CHUNK1 1024         // n per CTA in kernel 1 -> grid.y = 16
#define NCHUNK1 (NN / CHUNK1)

// Kernel-2 tiling
#define CHUNK2 2048         // n per CTA in kernel 2 -> grid.y = 8
#define NCHUNK2 (NN / CHUNK2)

// Scratch (allocation-free): unnormalized context U and exp-sums S per (b,h)
__device__ float g_U[NBH * HK * HK];   // [bh][kk][vv]
__device__ float g_S[NBH * HK];        // [bh][kk]

// ---------------------------------------------------------------------------
// Kernel 0: zero the scratch accumulators
// ---------------------------------------------------------------------------
__global__ void zero_scratch_kernel() {
    int i = blockIdx.x * blockDim.x + threadIdx.x;
    if (i < NBH * HK * HK) g_U[i] = 0.f;
    if (i < NBH * HK)      g_S[i] = 0.f;
}

// ---------------------------------------------------------------------------
// Kernel 1: per (b,h):  U[kk][vv] = sum_n exp(k[kk,n]) * v[vv,n]
//                       S[kk]     = sum_n exp(k[kk,n])
// grid = (64, 16), block = 256
// ---------------------------------------------------------------------------
__global__ void __launch_bounds__(256, 1)
context_kernel(const float* __restrict__ x1, const float* __restrict__ x2) {
    __shared__ __align__(16) float e_s[HK * PAD];
    __shared__ __align__(16) float v_s[HK * PAD];
    __shared__ float U_s[HK * HK];

    const int tid   = threadIdx.x;
    const int bh    = blockIdx.x;
    const int chunk = blockIdx.y;
    const int warp  = tid >> 5;
    const int lane  = tid & 31;

    // load-phase mapping: 64 threads per row (float4), 4 rows per pass
    const int lrow = tid >> 6;          // 0..3
    const int lcol = (tid & 63) << 2;   // 0..252 step 4

    // compute-phase thread mapping: 16 groups of 16 threads; each thread owns
    // a 4x4 subtile of U; group g handles n positions { (g + 16j)*4 .. +3 }
    const int g    = tid >> 4;
    const int t16  = tid & 15;
    const int kk0  = (t16 >> 2) << 2;
    const int vv0  = (t16 & 3) << 2;

    const float* kb = x2 + (size_t)bh * HK * NN;
    const float* vb = x1 + (size_t)bh * HK * NN;

    U_s[tid] = 0.f;

    float acc[4][4];
#pragma unroll
    for (int i = 0; i < 4; i++)
#pragma unroll
        for (int l = 0; l < 4; l++) acc[i][l] = 0.f;

    float sS0 = 0.f, sS1 = 0.f;   // warp w accumulates rows 2w, 2w+1 of S

    const int n_start = chunk * CHUNK1;

    for (int t = 0; t < CHUNK1 / TN; t++) {
        const int n0 = n_start + t * TN;

        // ---- load tile with float4: 4 rows per pass, 4 passes per array ----
#pragma unroll
        for (int p = 0; p < 4; p++) {
            const int r = lrow + 4 * p;
            float4 kv = *reinterpret_cast<const float4*>(&kb[(size_t)r * NN + n0 + lcol]);
            float4 vv = *reinterpret_cast<const float4*>(&vb[(size_t)r * NN + n0 + lcol]);
            float4 ev;
            ev.x = __expf(kv.x); ev.y = __expf(kv.y);
            ev.z = __expf(kv.z); ev.w = __expf(kv.w);
            *reinterpret_cast<float4*>(&e_s[r * PAD + lcol]) = ev;
            *reinterpret_cast<float4*>(&v_s[r * PAD + lcol]) = vv;
        }
        __syncthreads();

        // ---- S partial sums (warp w: rows 2w and 2w+1) ----
        {
            float s0 = 0.f, s1 = 0.f;
#pragma unroll
            for (int c = 0; c < TN / 32; c++) {
                s0 += e_s[(2 * warp) * PAD + lane + c * 32];
                s1 += e_s[(2 * warp + 1) * PAD + lane + c * 32];
            }
            sS0 += s0; sS1 += s1;
        }

        // ---- register-tiled rank-TN update of U ----
#pragma unroll
        for (int j = 0; j < TN / 64; j++) {
            const int n = (g + j * 16) * 4;
            float4 ee[4], vv4[4];
#pragma unroll
            for (int i = 0; i < 4; i++) {
                ee[i]  = *reinterpret_cast<const float4*>(&e_s[(kk0 + i) * PAD + n]);
                vv4[i] = *reinterpret_cast<const float4*>(&v_s[(vv0 + i) * PAD + n]);
            }
#pragma unroll
            for (int i = 0; i < 4; i++)
#pragma unroll
                for (int l = 0; l < 4; l++) {
                    acc[i][l] += ee[i].x * vv4[l].x;
                    acc[i][l] += ee[i].y * vv4[l].y;
                    acc[i][l] += ee[i].z * vv4[l].z;
                    acc[i][l] += ee[i].w * vv4[l].w;
                }
        }
        __syncthreads();   // protect smem before next tile's loads
    }

    // ---- reduce the 16 group-partials via smem atomics ----
#pragma unroll
    for (int i = 0; i < 4; i++)
#pragma unroll
        for (int l = 0; l < 4; l++)
            atomicAdd(&U_s[(kk0 + i) * HK + vv0 + l], acc[i][l]);

    // ---- S warp reduction + global atomics ----
#pragma unroll
    for (int off = 16; off > 0; off >>= 1) {
        sS0 += __shfl_down_sync(0xFFFFFFFFu, sS0, off);
        sS1 += __shfl_down_sync(0xFFFFFFFFu, sS1, off);
    }
    if (lane == 0) {
        atomicAdd(&g_S[bh * HK + 2 * warp],     sS0);
        atomicAdd(&g_S[bh * HK + 2 * warp + 1], sS1);
    }

    __syncthreads();
    atomicAdd(&g_U[bh * HK * HK + tid], U_s[tid]);
}

// ---------------------------------------------------------------------------
// Kernel 2: per n: q_sm = softmax_kk(k[:,n]);  out[vv,n] = sum_kk C[kk][vv]*q_sm[kk]
// where C[kk][vv] = U[kk][vv] / S[kk].
// grid = (64, 8), block = 256, each thread handles 2 n's per iteration.
// ---------------------------------------------------------------------------
__global__ void __launch_bounds__(256, 1)
attend_kernel(const float* __restrict__ x2, float* __restrict__ out) {
    __shared__ float C_s[HK * HK];

    const int tid = threadIdx.x;
    const int bh  = blockIdx.x;

    {
        const int kk = tid >> 4;
        C_s[tid] = g_U[bh * HK * HK + tid] / g_S[bh * HK + kk];
    }
    __syncthreads();

    const float* kb = x2 + (size_t)bh * HK * NN;
    float*       ob = out + (size_t)bh * HK * NN;

    const int base0 = blockIdx.y * CHUNK2;

    for (int base = base0; base < base0 + CHUNK2; base += 512) {
        const int n0 = base + tid;
        const int n1 = n0 + 256;

        float q0[HK], q1[HK];
#pragma unroll
        for (int kk = 0; kk < HK; kk++) {
            q0[kk] = kb[(size_t)kk * NN + n0];
            q1[kk] = kb[(size_t)kk * NN + n1];
        }

        // 16-channel softmax (with max subtraction, it's cheap)
        float m0 = q0[0], m1 = q1[0];
#pragma unroll
        for (int kk = 1; kk < HK; kk++) {
            m0 = fmaxf(m0, q0[kk]);
            m1 = fmaxf(m1, q1[kk]);
        }
        float s0 = 0.f, s1 = 0.f;
#pragma unroll
        for (int kk = 0; kk < HK; kk++) {
            q0[kk] = __expf(q0[kk] - m0); s0 += q0[kk];
            q1[kk] = __expf(q1[kk] - m1); s1 += q1[kk];
        }
        const float r0 = 1.f / s0, r1 = 1.f / s1;

        float o0[HK], o1[HK];
#pragma unroll
        for (int vv = 0; vv < HK; vv++) { o0[vv] = 0.f; o1[vv] = 0.f; }

#pragma unroll
        for (int kk = 0; kk < HK; kk++) {
            const float e0 = q0[kk], e1 = q1[kk];
#pragma unroll
            for (int vv = 0; vv < HK; vv++) {
                const float c = C_s[kk * HK + vv];   // uniform -> smem broadcast
                o0[vv] += c * e0;
                o1[vv] += c * e1;
            }
        }

#pragma unroll
        for (int vv = 0; vv < HK; vv++) {
            ob[(size_t)vv * NN + n0] = o0[vv] * r0;
            ob[(size_t)vv * NN + n1] = o1[vv] * r1;
        }
    }
}

// ---------------------------------------------------------------------------
extern "C" void kernel_launch(void* const* d_in, const int* in_sizes, int n_in,
                              void* d_out, int out_size) {
    const float* x1 = (const float*)d_in[0];   // values
    const float* x2 = (const float*)d_in[1];   // keys/queries
    float* out = (float*)d_out;

    zero_scratch_kernel<<<(NBH * HK * HK + 255) / 256, 256>>>();

    dim3 grid1(NBH, NCHUNK1);
    context_kernel<<<grid1, 256>>>(x1, x2);

    dim3 grid2(NBH, NCHUNK2);
    attend_kernel<<<grid2, 256>>>(x2, out);
}

// round 3
// speedup vs baseline: 1.1050x; 1.1050x over previous
#include <cuda_runtime.h>
#include <cuda_bf16.h>
#include <cstdint>

// Problem constants
#define NB 8
#define NC 128
#define NHEADS 8
#define NN 16384            // H*W
#define HK 16               // channels per head
#define NBH 64              // NB*NHEADS

// Kernel-1 tiling
#define TN 256              // n-tile held in smem
#define PAD 260             // padded row stride (floats), multiple of 4 for float4
#define CHUNK1 1024         // n per CTA in kernel 1 -> grid.y = 16
#define NCHUNK1 (NN / CHUNK1)

// Kernel-2 tiling
#define CHUNK2 2048         // n per CTA in kernel 2 -> grid.y = 8
#define NCHUNK2 (NN / CHUNK2)

// Scratch (allocation-free): per-chunk PARTIAL context / exp-sums, no atomics.
// Each context CTA owns its [bh][chunk] slice; attend reduces over chunks.
__device__ float g_Up[NBH * NCHUNK1 * HK * HK];  // [bh][chunk][kk*16+vv]
__device__ float g_Sp[NBH * NCHUNK1 * HK];       // [bh][chunk][kk]

// ---------------------------------------------------------------------------
// Kernel 1: per (b,h,chunk):
//   Up[kk][vv] = sum_{n in chunk} exp(k[kk,n]) * v[vv,n]
//   Sp[kk]     = sum_{n in chunk} exp(k[kk,n])
// grid = (64, 16), block = 256
// ---------------------------------------------------------------------------
__global__ void __launch_bounds__(256)
context_kernel(const float* __restrict__ x1, const float* __restrict__ x2) {
    __shared__ __align__(16) float e_s[HK * PAD];
    __shared__ __align__(16) float v_s[HK * PAD];
    __shared__ float U_s[HK * HK];

    const int tid   = threadIdx.x;
    const int bh    = blockIdx.x;
    const int chunk = blockIdx.y;
    const int warp  = tid >> 5;
    const int lane  = tid & 31;

    // load-phase mapping: 64 threads per row (float4), 4 rows per pass
    const int lrow = tid >> 6;          // 0..3
    const int lcol = (tid & 63) << 2;   // 0..252 step 4

    // compute-phase: 16 groups of 16 threads; each thread owns a 4x4 subtile
    const int g    = tid >> 4;
    const int t16  = tid & 15;
    const int kk0  = (t16 >> 2) << 2;
    const int vv0  = (t16 & 3) << 2;

    const float* kb = x2 + (size_t)bh * HK * NN;
    const float* vb = x1 + (size_t)bh * HK * NN;

    U_s[tid] = 0.f;

    float acc[4][4];
#pragma unroll
    for (int i = 0; i < 4; i++)
#pragma unroll
        for (int l = 0; l < 4; l++) acc[i][l] = 0.f;

    float sS0 = 0.f, sS1 = 0.f;   // warp w accumulates rows 2w, 2w+1 of S

    const int n_start = chunk * CHUNK1;

    for (int t = 0; t < CHUNK1 / TN; t++) {
        const int n0 = n_start + t * TN;

        // ---- load tile with float4: 4 rows per pass, 4 passes ----
#pragma unroll
        for (int p = 0; p < 4; p++) {
            const int r = lrow + 4 * p;
            float4 kv = *reinterpret_cast<const float4*>(&kb[(size_t)r * NN + n0 + lcol]);
            float4 vv = *reinterpret_cast<const float4*>(&vb[(size_t)r * NN + n0 + lcol]);
            float4 ev;
            ev.x = __expf(kv.x); ev.y = __expf(kv.y);
            ev.z = __expf(kv.z); ev.w = __expf(kv.w);
            *reinterpret_cast<float4*>(&e_s[r * PAD + lcol]) = ev;
            *reinterpret_cast<float4*>(&v_s[r * PAD + lcol]) = vv;
        }
        __syncthreads();

        // ---- S partial sums (warp w: rows 2w and 2w+1) ----
        {
            float s0 = 0.f, s1 = 0.f;
#pragma unroll
            for (int c = 0; c < TN / 32; c++) {
                s0 += e_s[(2 * warp) * PAD + lane + c * 32];
                s1 += e_s[(2 * warp + 1) * PAD + lane + c * 32];
            }
            sS0 += s0; sS1 += s1;
        }

        // ---- register-tiled rank-TN update of U ----
#pragma unroll
        for (int j = 0; j < TN / 64; j++) {
            const int n = (g + j * 16) * 4;
            float4 ee[4], vv4[4];
#pragma unroll
            for (int i = 0; i < 4; i++) {
                ee[i]  = *reinterpret_cast<const float4*>(&e_s[(kk0 + i) * PAD + n]);
                vv4[i] = *reinterpret_cast<const float4*>(&v_s[(vv0 + i) * PAD + n]);
            }
#pragma unroll
            for (int i = 0; i < 4; i++)
#pragma unroll
                for (int l = 0; l < 4; l++) {
                    acc[i][l] += ee[i].x * vv4[l].x;
                    acc[i][l] += ee[i].y * vv4[l].y;
                    acc[i][l] += ee[i].z * vv4[l].z;
                    acc[i][l] += ee[i].w * vv4[l].w;
                }
        }
        __syncthreads();   // protect smem before next tile's loads
    }

    // ---- reduce the 16 group-partials via smem atomics (fast, spread) ----
#pragma unroll
    for (int i = 0; i < 4; i++)
#pragma unroll
        for (int l = 0; l < 4; l++)
            atomicAdd(&U_s[(kk0 + i) * HK + vv0 + l], acc[i][l]);

    // ---- S warp reduction -> owned global slice (plain stores) ----
#pragma unroll
    for (int off = 16; off > 0; off >>= 1) {
        sS0 += __shfl_down_sync(0xFFFFFFFFu, sS0, off);
        sS1 += __shfl_down_sync(0xFFFFFFFFu, sS1, off);
    }
    if (lane == 0) {
        g_Sp[(bh * NCHUNK1 + chunk) * HK + 2 * warp]     = sS0;
        g_Sp[(bh * NCHUNK1 + chunk) * HK + 2 * warp + 1] = sS1;
    }

    __syncthreads();
    g_Up[(bh * NCHUNK1 + chunk) * HK * HK + tid] = U_s[tid];
}

// ---------------------------------------------------------------------------
// Kernel 2: reduce partials -> C; then per n:
//   q_sm = softmax_kk(k[:,n]);  out[vv,n] = sum_kk C[kk][vv]*q_sm[kk]
// grid = (64, 8), block = 256; each thread handles 4 contiguous n per iter.
// ---------------------------------------------------------------------------
__global__ void __launch_bounds__(256)
attend_kernel(const float* __restrict__ x2, float* __restrict__ out) {
    __shared__ float C_s[HK * HK];
    __shared__ float S_s[HK];

    const int tid = threadIdx.x;
    const int bh  = blockIdx.x;

    // ---- reduce U partials over chunks (each thread owns one U element) ----
    float u = 0.f;
#pragma unroll
    for (int c = 0; c < NCHUNK1; c++)
        u += g_Up[(bh * NCHUNK1 + c) * HK * HK + tid];

    // ---- reduce S partials (threads 0..15) ----
    if (tid < HK) {
        float s = 0.f;
#pragma unroll
        for (int c = 0; c < NCHUNK1; c++)
            s += g_Sp[(bh * NCHUNK1 + c) * HK + tid];
        S_s[tid] = s;
    }
    __syncthreads();
    C_s[tid] = u / S_s[tid >> 4];
    __syncthreads();

    const float* kb = x2 + (size_t)bh * HK * NN;
    float*       ob = out + (size_t)bh * HK * NN;

    const int base0 = blockIdx.y * CHUNK2;

    // each iter covers 1024 n (256 threads x 4), CHUNK2/1024 = 2 iters
    for (int base = base0; base < base0 + CHUNK2; base += 1024) {
        const int n0 = base + (tid << 2);

        // ---- load q[16] as float4 (16 independent LDG.128, MLP=16) ----
        float4 q[HK];
#pragma unroll
        for (int kk = 0; kk < HK; kk++)
            q[kk] = *reinterpret_cast<const float4*>(&kb[(size_t)kk * NN + n0]);

        // ---- 16-channel softmax over kk, per lane of the float4 ----
        float4 m = q[0];
#pragma unroll
        for (int kk = 1; kk < HK; kk++) {
            m.x = fmaxf(m.x, q[kk].x); m.y = fmaxf(m.y, q[kk].y);
            m.z = fmaxf(m.z, q[kk].z); m.w = fmaxf(m.w, q[kk].w);
        }
        float4 s = make_float4(0.f, 0.f, 0.f, 0.f);
#pragma unroll
        for (int kk = 0; kk < HK; kk++) {
            q[kk].x = __expf(q[kk].x - m.x); s.x += q[kk].x;
            q[kk].y = __expf(q[kk].y - m.y); s.y += q[kk].y;
            q[kk].z = __expf(q[kk].z - m.z); s.z += q[kk].z;
            q[kk].w = __expf(q[kk].w - m.w); s.w += q[kk].w;
        }
        const float4 r = make_float4(1.f / s.x, 1.f / s.y, 1.f / s.z, 1.f / s.w);

        // ---- out[vv] = (sum_kk C[kk][vv] * e[kk]) * r ; store immediately ----
#pragma unroll
        for (int vv = 0; vv < HK; vv++) {
            float4 o = make_float4(0.f, 0.f, 0.f, 0.f);
#pragma unroll
            for (int kk = 0; kk < HK; kk++) {
                const float c = C_s[kk * HK + vv];   // uniform -> smem broadcast
                o.x += c * q[kk].x;
                o.y += c * q[kk].y;
                o.z += c * q[kk].z;
                o.w += c * q[kk].w;
            }
            o.x *= r.x; o.y *= r.y; o.z *= r.z; o.w *= r.w;
            *reinterpret_cast<float4*>(&ob[(size_t)vv * NN + n0]) = o;
        }
    }
}

// ---------------------------------------------------------------------------
extern "C" void kernel_launch(void* const* d_in, const int* in_sizes, int n_in,
                              void* d_out, int out_size) {
    const float* x1 = (const float*)d_in[0];   // values
    const float* x2 = (const float*)d_in[1];   // keys/queries
    float* out = (float*)d_out;

    dim3 grid1(NBH, NCHUNK1);
    context_kernel<<<grid1, 256>>>(x1, x2);

    dim3 grid2(NBH, NCHUNK2);
    attend_kernel<<<grid2, 256>>>(x2, out);
}